// round 15
// baseline (speedup 1.0000x reference)
#include <cuda_runtime.h>
#include <cuda_bf16.h>
#include <cuda_fp16.h>
#include <cstdint>

#define N_TOK 1024
#define DH    64
#define NB    8
#define NGH   4
#define NLH   8
#define NLVL  4
#define NN    (N_TOK * N_TOK)
#define NBG   (NB * NGH)          // 32
#define KSTEPS 8                  // tf32 m16n8k8, K=64
#define SROWF  68                 // staging row stride in fp32 (272 B)
#define SBROW  136                // bounce row stride in half (272 B)

typedef unsigned long long u64t;

// ---------------- scratch ----------------
__device__ __half g_S[(size_t)NBG * NN];                      // 64 MB

__device__ __forceinline__ uint32_t smem_u32(const void* p) {
    uint32_t a;
    asm("{ .reg .u64 t; cvta.to.shared.u64 t, %1; cvt.u32.u64 %0, t; }" : "=r"(a) : "l"(p));
    return a;
}
__device__ __forceinline__ uint32_t f2tf32(float v) {
    uint32_t r; asm("cvt.rna.tf32.f32 %0, %1;" : "=r"(r) : "f"(v)); return r;
}

// ---------------- packed f32x2 helpers ----------------
__device__ __forceinline__ u64t pack2(float a, float b) {
    u64t r; asm("mov.b64 %0, {%1, %2};" : "=l"(r) : "f"(a), "f"(b)); return r;
}
__device__ __forceinline__ void unpack2(u64t p, float& a, float& b) {
    asm("mov.b64 {%0, %1}, %2;" : "=f"(a), "=f"(b) : "l"(p));
}
__device__ __forceinline__ u64t mul2(u64t a, u64t b) {
    u64t d; asm("mul.rn.f32x2 %0, %1, %2;" : "=l"(d) : "l"(a), "l"(b)); return d;
}
__device__ __forceinline__ u64t fma2(u64t a, u64t b, u64t c) {
    u64t d; asm("fma.rn.f32x2 %0, %1, %2, %3;" : "=l"(d) : "l"(a), "l"(b), "l"(c)); return d;
}

// streaming (evict-first) memory ops
__device__ __forceinline__ uint32_t ldcs_u32(const void* p) {
    uint32_t v; asm volatile("ld.global.cs.b32 %0, [%1];" : "=r"(v) : "l"(p)); return v;
}
__device__ __forceinline__ float4 ldcs_f4(const void* p) {
    float4 v;
    asm volatile("ld.global.cs.v4.f32 {%0,%1,%2,%3}, [%4];"
                 : "=f"(v.x), "=f"(v.y), "=f"(v.z), "=f"(v.w) : "l"(p));
    return v;
}
__device__ __forceinline__ void stcs_u64(void* p, u64t v) {
    asm volatile("st.global.cs.b64 [%0], %1;" :: "l"(p), "l"(v) : "memory");
}

// ---------------------------------------------------------------------------
// Kernel 1: tf32 mma.sync GEMM (m16n8k8), K=64 — EXACT Round-14 version.
// ---------------------------------------------------------------------------
#define SM_BYTES (2 * 128 * SROWF * 4)    // 69632

__global__ __launch_bounds__(256)
void qk_gemm_mma(const float* __restrict__ q, const float* __restrict__ k)
{
    extern __shared__ __align__(16) char smem[];
    float* As = (float*)smem;               // [128][SROWF]
    float* Bs = As + 128 * SROWF;

    const int tid  = threadIdx.x;
    const int lane = tid & 31;
    const int w    = tid >> 5;
    const int wm   = (w & 1) * 64;
    const int wn   = (w >> 1) * 32;

    const int bg = blockIdx.z;
    const int qt = blockIdx.y * 128;
    const int kt = blockIdx.x * 128;

    const float* Qg = q + ((size_t)bg * N_TOK + qt) * DH;
    const float* Kg = k + ((size_t)bg * N_TOK + kt) * DH;

#pragma unroll
    for (int it = 0; it < 8; it++) {
        int idx = it * 256 + tid;
        int row = idx >> 4;
        int c4  = (idx & 15) * 4;
        float4 qv = *(const float4*)(Qg + (size_t)row * DH + c4);
        float4 kv = *(const float4*)(Kg + (size_t)row * DH + c4);
        *(uint4*)(As + row * SROWF + c4) =
            make_uint4(f2tf32(qv.x), f2tf32(qv.y), f2tf32(qv.z), f2tf32(qv.w));
        *(uint4*)(Bs + row * SROWF + c4) =
            make_uint4(f2tf32(kv.x), f2tf32(kv.y), f2tf32(kv.z), f2tf32(kv.w));
    }
    __syncthreads();

    const uint32_t a_base = smem_u32(As);
    const uint32_t b_base = smem_u32(Bs);

    const int arow  = lane & 15;
    const int akoff = (lane >> 4) * 4;
    const int brow  = (lane & 7) + ((lane >> 4) << 3);
    const int bkoff = ((lane >> 3) & 1) * 4;

    float acc[4][4][4];
#pragma unroll
    for (int mi = 0; mi < 4; mi++)
#pragma unroll
        for (int ni = 0; ni < 4; ni++)
#pragma unroll
            for (int r = 0; r < 4; r++) acc[mi][ni][r] = 0.0f;

#pragma unroll
    for (int s = 0; s < KSTEPS; s++) {
        const int k0 = s * 8;

        uint32_t af[4][4], bf[4][2];
#pragma unroll
        for (int mi = 0; mi < 4; mi++) {
            uint32_t addr = a_base + (uint32_t)(((wm + mi * 16 + arow) * SROWF + k0 + akoff) * 4);
            asm volatile("ldmatrix.sync.aligned.m8n8.x4.shared.b16 {%0,%1,%2,%3}, [%4];"
                         : "=r"(af[mi][0]), "=r"(af[mi][1]), "=r"(af[mi][2]), "=r"(af[mi][3])
                         : "r"(addr));
        }
#pragma unroll
        for (int nip = 0; nip < 2; nip++) {
            uint32_t addr = b_base + (uint32_t)(((wn + nip * 16 + brow) * SROWF + k0 + bkoff) * 4);
            asm volatile("ldmatrix.sync.aligned.m8n8.x4.shared.b16 {%0,%1,%2,%3}, [%4];"
                         : "=r"(bf[2 * nip][0]), "=r"(bf[2 * nip][1]),
                           "=r"(bf[2 * nip + 1][0]), "=r"(bf[2 * nip + 1][1])
                         : "r"(addr));
        }
#pragma unroll
        for (int mi = 0; mi < 4; mi++)
#pragma unroll
            for (int ni = 0; ni < 4; ni++) {
                asm volatile(
                    "mma.sync.aligned.m16n8k8.row.col.f32.tf32.tf32.f32 "
                    "{%0,%1,%2,%3}, {%4,%5,%6,%7}, {%8,%9}, {%0,%1,%2,%3};"
                    : "+f"(acc[mi][ni][0]), "+f"(acc[mi][ni][1]),
                      "+f"(acc[mi][ni][2]), "+f"(acc[mi][ni][3])
                    : "r"(af[mi][0]), "r"(af[mi][1]), "r"(af[mi][2]), "r"(af[mi][3]),
                      "r"(bf[ni][0]), "r"(bf[ni][1]));
            }
    }

    __syncthreads();
    __half* Sb = (__half*)smem;           // [128][SBROW]
#pragma unroll
    for (int mi = 0; mi < 4; mi++) {
#pragma unroll
        for (int ni = 0; ni < 4; ni++) {
            int m = wm + mi * 16 + (lane >> 2);
            int n = wn + ni * 8 + (lane & 3) * 2;
            *(__half2*)(Sb + m * SBROW + n) =
                __floats2half2_rn(acc[mi][ni][0], acc[mi][ni][1]);
            *(__half2*)(Sb + (m + 8) * SBROW + n) =
                __floats2half2_rn(acc[mi][ni][2], acc[mi][ni][3]);
        }
    }
    __syncthreads();

    __half* __restrict__ Sp = g_S + (size_t)bg * NN;
    const int rr = tid >> 4;
    const int cc = (tid & 15) * 8;
#pragma unroll
    for (int it = 0; it < 8; it++) {
        int row = it * 16 + rr;
        uint4 v = *(const uint4*)(Sb + row * SBROW + cc);
        *(uint4*)(Sp + (size_t)(qt + row) * N_TOK + kt + cc) = v;
    }
}

// ---------------------------------------------------------------------------
// Kernel 2: epilogue, f32x2 packed over the i-pair {i0, i0+1}.
// Same loads/stores/traffic as R14; the lane re-packing removes the per-b
// broadcast pack churn and halves the v-vector registers -> 4 CTAs/SM.
// ---------------------------------------------------------------------------
__global__ __launch_bounds__(128, 4)
void epilogue_kernel(const float* __restrict__ masks,
                     const float* __restrict__ proj,   // [4][32]
                     const float* __restrict__ hw,     // [8][8]
                     const float* __restrict__ hb,     // [8]
                     float* __restrict__ out)
{
    __shared__ u64t sPb[128];   // [l][x] broadcast {P,P}
    __shared__ u64t sWb[64];    // [h][hh] broadcast {W,W}
    __shared__ u64t sBb[8];     // broadcast {hb,hb}

    const int tid = threadIdx.x;
    if (tid < 128) { float v = proj[tid]; sPb[tid] = pack2(v, v); }
    if (tid < 64)  { float v = hw[tid];   sWb[tid] = pack2(v, v); }
    if (tid < 8)   { float v = hb[tid];   sBb[tid] = pack2(v, v); }
    __syncthreads();

    const size_t i0 = 2 * ((size_t)blockIdx.x * 128 + tid);   // i-pair {i0, i0+1}
    const __half* __restrict__ Sp = g_S + i0;

    // all 32 independent streaming S loads up front (half2 = 1 reg each)
    __half2 sh[NBG];
#pragma unroll
    for (int j = 0; j < NBG; j++) {
        uint32_t bits = ldcs_u32(Sp + ((size_t)j << 20));
        sh[j] = *(__half2*)&bits;
    }

    float4 ma = ldcs_f4(masks + 4 * i0);        // masks for i0
    float4 mb = ldcs_f4(masks + 4 * i0 + 4);    // masks for i0+1

    // mask-mix weights packed over i: mw2[x] lanes = {mw_i0[x], mw_i1[x]}
    u64t mw2[32];
    {
        u64t ml0 = pack2(ma.x, mb.x), ml1 = pack2(ma.y, mb.y);
        u64t ml2 = pack2(ma.z, mb.z), ml3 = pack2(ma.w, mb.w);
#pragma unroll
        for (int x = 0; x < 32; x++) {
            u64t t = mul2(ml0, sPb[x]);
            t = fma2(ml1, sPb[32 + x], t);
            t = fma2(ml2, sPb[64 + x], t);
            t = fma2(ml3, sPb[96 + x], t);
            mw2[x] = t;
        }
    }

#pragma unroll
    for (int b = 0; b < NB; b++) {
        // S operands packed over i, straight from half2
        float2 f0 = __half22float2(sh[b * 4 + 0]);
        float2 f1 = __half22float2(sh[b * 4 + 1]);
        float2 f2 = __half22float2(sh[b * 4 + 2]);
        float2 f3 = __half22float2(sh[b * 4 + 3]);
        u64t s0 = pack2(f0.x, f0.y), s1 = pack2(f1.x, f1.y);
        u64t s2 = pack2(f2.x, f2.y), s3 = pack2(f3.x, f3.y);

        // mix over g + relu (packed over i)
        u64t v2[8];
#pragma unroll
        for (int h = 0; h < 8; h++) {
            u64t t = mul2(s0, mw2[h]);
            t = fma2(s1, mw2[8 + h], t);
            t = fma2(s2, mw2[16 + h], t);
            t = fma2(s3, mw2[24 + h], t);
            float a, c; unpack2(t, a, c);
            v2[h] = pack2(fmaxf(a, 0.0f), fmaxf(c, 0.0f));
        }

        // head projection (packed over i) + direct 8-byte streaming stores
#pragma unroll
        for (int h = 0; h < 8; h++) {
            u64t o = sBb[h];
#pragma unroll
            for (int hh = 0; hh < 8; hh++)
                o = fma2(v2[hh], sWb[h * 8 + hh], o);
            stcs_u64(out + ((size_t)(b * 8 + h) << 20) + i0, o);
        }
    }
}

extern "C" void kernel_launch(void* const* d_in, const int* in_sizes, int n_in,
                              void* d_out, int out_size)
{
    const float* q     = (const float*)d_in[0];
    const float* k     = (const float*)d_in[1];
    const float* masks = (const float*)d_in[2];
    const float* proj  = (const float*)d_in[3];
    const float* hw    = (const float*)d_in[4];
    const float* hb    = (const float*)d_in[5];
    float* out = (float*)d_out;

    cudaFuncSetAttribute(qk_gemm_mma, cudaFuncAttributeMaxDynamicSharedMemorySize, SM_BYTES);

    dim3 g1(N_TOK / 128, N_TOK / 128, NBG);
    qk_gemm_mma<<<g1, 256, SM_BYTES>>>(q, k);

    epilogue_kernel<<<NN / 256, 128>>>(masks, proj, hw, hb, out);
}

// round 16
// speedup vs baseline: 1.6566x; 1.6566x over previous
#include <cuda_runtime.h>
#include <cuda_bf16.h>
#include <cuda_fp16.h>
#include <cstdint>

#define N_TOK 1024
#define DH    64
#define NB    8
#define NGH   4
#define NLH   8
#define NLVL  4
#define NN    (N_TOK * N_TOK)
#define NBG   (NB * NGH)          // 32
#define KSTEPS 8                  // tf32 m16n8k8, K=64
#define SROWF  68                 // staging row stride in fp32 (272 B)
#define SBROW2 72                 // bounce row stride in half (144 B) for 64-wide tile

typedef unsigned long long u64t;

// ---------------- scratch ----------------
__device__ __half g_S[(size_t)NBG * NN];                      // 64 MB

__device__ __forceinline__ uint32_t smem_u32(const void* p) {
    uint32_t a;
    asm("{ .reg .u64 t; cvta.to.shared.u64 t, %1; cvt.u32.u64 %0, t; }" : "=r"(a) : "l"(p));
    return a;
}
__device__ __forceinline__ uint32_t f2tf32(float v) {
    uint32_t r; asm("cvt.rna.tf32.f32 %0, %1;" : "=r"(r) : "f"(v)); return r;
}

// ---------------- packed f32x2 helpers ----------------
__device__ __forceinline__ u64t pack2(float a, float b) {
    u64t r; asm("mov.b64 %0, {%1, %2};" : "=l"(r) : "f"(a), "f"(b)); return r;
}
__device__ __forceinline__ void unpack2(u64t p, float& a, float& b) {
    asm("mov.b64 {%0, %1}, %2;" : "=f"(a), "=f"(b) : "l"(p));
}
__device__ __forceinline__ u64t mul2(u64t a, u64t b) {
    u64t d; asm("mul.rn.f32x2 %0, %1, %2;" : "=l"(d) : "l"(a), "l"(b)); return d;
}
__device__ __forceinline__ u64t fma2(u64t a, u64t b, u64t c) {
    u64t d; asm("fma.rn.f32x2 %0, %1, %2, %3;" : "=l"(d) : "l"(a), "l"(b), "l"(c)); return d;
}

// streaming (evict-first) memory ops
__device__ __forceinline__ uint32_t ldcs_u32(const void* p) {
    uint32_t v; asm volatile("ld.global.cs.b32 %0, [%1];" : "=r"(v) : "l"(p)); return v;
}
__device__ __forceinline__ float4 ldcs_f4(const void* p) {
    float4 v;
    asm volatile("ld.global.cs.v4.f32 {%0,%1,%2,%3}, [%4];"
                 : "=f"(v.x), "=f"(v.y), "=f"(v.z), "=f"(v.w) : "l"(p));
    return v;
}
__device__ __forceinline__ void stcs_u64(void* p, u64t v) {
    asm volatile("st.global.cs.b64 [%0], %1;" :: "l"(p), "l"(v) : "memory");
}

// ---------------------------------------------------------------------------
// Kernel 1: tf32 mma.sync GEMM (m16n8k8), K=64.
// Tile 128(q) x 64(k), 128 threads = 4 warps (2x2, warp tile 64x32).
// Per-thread work identical to the proven 256-thread version, but half the
// threads per CTA -> 4 CTAs/SM resident (reg cap 128, ~105 used, NO spill)
// -> 2x the cross-CTA stage/MMA/store phase overlap.
// ---------------------------------------------------------------------------
#define A_FLOATS (128 * SROWF)
#define B_FLOATS (64 * SROWF)
#define SM_BYTES ((A_FLOATS + B_FLOATS) * 4)    // 52224

__global__ __launch_bounds__(128, 4)
void qk_gemm_mma(const float* __restrict__ q, const float* __restrict__ k)
{
    extern __shared__ __align__(16) char smem[];
    float* As = (float*)smem;               // [128][SROWF]
    float* Bs = As + A_FLOATS;              // [64][SROWF]

    const int tid  = threadIdx.x;
    const int lane = tid & 31;
    const int w    = tid >> 5;              // 0..3
    const int wm   = (w & 1) * 64;
    const int wn   = (w >> 1) * 32;

    const int bg = blockIdx.z;
    const int qt = blockIdx.y * 128;
    const int kt = blockIdx.x * 64;

    const float* Qg = q + ((size_t)bg * N_TOK + qt) * DH;
    const float* Kg = k + ((size_t)bg * N_TOK + kt) * DH;

    // --- stage A: 128 rows x 64 fp32 (16 uint4/row) ---
#pragma unroll
    for (int it = 0; it < 16; it++) {
        int idx = it * 128 + tid;
        int row = idx >> 4;
        int c4  = (idx & 15) * 4;
        float4 qv = *(const float4*)(Qg + (size_t)row * DH + c4);
        *(uint4*)(As + row * SROWF + c4) =
            make_uint4(f2tf32(qv.x), f2tf32(qv.y), f2tf32(qv.z), f2tf32(qv.w));
    }
    // --- stage B: 64 rows x 64 fp32 ---
#pragma unroll
    for (int it = 0; it < 8; it++) {
        int idx = it * 128 + tid;
        int row = idx >> 4;
        int c4  = (idx & 15) * 4;
        float4 kv = *(const float4*)(Kg + (size_t)row * DH + c4);
        *(uint4*)(Bs + row * SROWF + c4) =
            make_uint4(f2tf32(kv.x), f2tf32(kv.y), f2tf32(kv.z), f2tf32(kv.w));
    }
    __syncthreads();

    const uint32_t a_base = smem_u32(As);
    const uint32_t b_base = smem_u32(Bs);

    const int arow  = lane & 15;
    const int akoff = (lane >> 4) * 4;
    const int brow  = (lane & 7) + ((lane >> 4) << 3);
    const int bkoff = ((lane >> 3) & 1) * 4;

    float acc[4][4][4];
#pragma unroll
    for (int mi = 0; mi < 4; mi++)
#pragma unroll
        for (int ni = 0; ni < 4; ni++)
#pragma unroll
            for (int r = 0; r < 4; r++) acc[mi][ni][r] = 0.0f;

#pragma unroll
    for (int s = 0; s < KSTEPS; s++) {
        const int k0 = s * 8;

        uint32_t af[4][4], bf[4][2];
#pragma unroll
        for (int mi = 0; mi < 4; mi++) {
            uint32_t addr = a_base + (uint32_t)(((wm + mi * 16 + arow) * SROWF + k0 + akoff) * 4);
            asm volatile("ldmatrix.sync.aligned.m8n8.x4.shared.b16 {%0,%1,%2,%3}, [%4];"
                         : "=r"(af[mi][0]), "=r"(af[mi][1]), "=r"(af[mi][2]), "=r"(af[mi][3])
                         : "r"(addr));
        }
#pragma unroll
        for (int nip = 0; nip < 2; nip++) {
            uint32_t addr = b_base + (uint32_t)(((wn + nip * 16 + brow) * SROWF + k0 + bkoff) * 4);
            asm volatile("ldmatrix.sync.aligned.m8n8.x4.shared.b16 {%0,%1,%2,%3}, [%4];"
                         : "=r"(bf[2 * nip][0]), "=r"(bf[2 * nip][1]),
                           "=r"(bf[2 * nip + 1][0]), "=r"(bf[2 * nip + 1][1])
                         : "r"(addr));
        }
#pragma unroll
        for (int mi = 0; mi < 4; mi++)
#pragma unroll
            for (int ni = 0; ni < 4; ni++) {
                asm volatile(
                    "mma.sync.aligned.m16n8k8.row.col.f32.tf32.tf32.f32 "
                    "{%0,%1,%2,%3}, {%4,%5,%6,%7}, {%8,%9}, {%0,%1,%2,%3};"
                    : "+f"(acc[mi][ni][0]), "+f"(acc[mi][ni][1]),
                      "+f"(acc[mi][ni][2]), "+f"(acc[mi][ni][3])
                    : "r"(af[mi][0]), "r"(af[mi][1]), "r"(af[mi][2]), "r"(af[mi][3]),
                      "r"(bf[ni][0]), "r"(bf[ni][1]));
            }
    }

    // --- bounce: fragments -> smem ---
    __syncthreads();
    __half* Sb = (__half*)smem;           // [128][SBROW2]
#pragma unroll
    for (int mi = 0; mi < 4; mi++) {
#pragma unroll
        for (int ni = 0; ni < 4; ni++) {
            int m = wm + mi * 16 + (lane >> 2);
            int n = wn + ni * 8 + (lane & 3) * 2;
            *(__half2*)(Sb + m * SBROW2 + n) =
                __floats2half2_rn(acc[mi][ni][0], acc[mi][ni][1]);
            *(__half2*)(Sb + (m + 8) * SBROW2 + n) =
                __floats2half2_rn(acc[mi][ni][2], acc[mi][ni][3]);
        }
    }
    __syncthreads();

    // --- readout: coalesced STG.128 (warp = 4 rows x 128B contiguous) ---
    __half* __restrict__ Sp = g_S + (size_t)bg * NN;
    const int rr = tid >> 3;              // 0..15
    const int cc = (tid & 7) * 8;         // half col, 16B chunks over 64 cols
#pragma unroll
    for (int it = 0; it < 8; it++) {
        int row = it * 16 + rr;
        uint4 v = *(const uint4*)(Sb + row * SBROW2 + cc);
        *(uint4*)(Sp + (size_t)(qt + row) * N_TOK + kt + cc) = v;
    }
}

// ---------------------------------------------------------------------------
// Kernel 2: epilogue — EXACT Round-14 version (proven 59.7 us; 168 regs,
// (128,3), h-pair f32x2 packing; do NOT cap regs to 128 — it spills).
// ---------------------------------------------------------------------------
__global__ __launch_bounds__(128, 3)
void epilogue_kernel(const float* __restrict__ masks,
                     const float* __restrict__ proj,   // [4][32]
                     const float* __restrict__ hw,     // [8][8]
                     const float* __restrict__ hb,     // [8]
                     float* __restrict__ out)
{
    __shared__ u64t sP2[64];
    __shared__ u64t sWt2[32];
    __shared__ u64t sB2[4];

    const int tid = threadIdx.x;
    if (tid < 64) {
        int l = tid >> 4, xp = tid & 15;
        sP2[tid] = pack2(proj[l * 32 + 2 * xp], proj[l * 32 + 2 * xp + 1]);
    }
    if (tid < 32) {
        int hh = tid >> 2, hp = tid & 3;
        sWt2[tid] = pack2(hw[(2 * hp) * 8 + hh], hw[(2 * hp + 1) * 8 + hh]);
    }
    if (tid < 4) sB2[tid] = pack2(hb[2 * tid], hb[2 * tid + 1]);
    __syncthreads();

    const size_t i0 = 2 * ((size_t)blockIdx.x * 128 + tid);
    const __half* __restrict__ Sp = g_S + i0;

    __half2 sh[NBG];
#pragma unroll
    for (int j = 0; j < NBG; j++) {
        uint32_t bits = ldcs_u32(Sp + ((size_t)j << 20));
        sh[j] = *(__half2*)&bits;
    }

    float4 ma = ldcs_f4(masks + 4 * i0);
    float4 mb = ldcs_f4(masks + 4 * i0 + 4);

    u64t mwA[16], mwB[16];
    {
        u64t ax = pack2(ma.x, ma.x), ay = pack2(ma.y, ma.y);
        u64t az = pack2(ma.z, ma.z), aw = pack2(ma.w, ma.w);
        u64t bx = pack2(mb.x, mb.x), by = pack2(mb.y, mb.y);
        u64t bz = pack2(mb.z, mb.z), bw = pack2(mb.w, mb.w);
#pragma unroll
        for (int xp = 0; xp < 16; xp++) {
            u64t p0 = sP2[xp], p1 = sP2[16 + xp], p2 = sP2[32 + xp], p3 = sP2[48 + xp];
            u64t tA = mul2(ax, p0);
            tA = fma2(ay, p1, tA);
            tA = fma2(az, p2, tA);
            tA = fma2(aw, p3, tA);
            mwA[xp] = tA;
            u64t tB = mul2(bx, p0);
            tB = fma2(by, p1, tB);
            tB = fma2(bz, p2, tB);
            tB = fma2(bw, p3, tB);
            mwB[xp] = tB;
        }
    }

#pragma unroll
    for (int b = 0; b < NB; b++) {
        float2 f0 = __half22float2(sh[b * 4 + 0]);
        float2 f1 = __half22float2(sh[b * 4 + 1]);
        float2 f2 = __half22float2(sh[b * 4 + 2]);
        float2 f3 = __half22float2(sh[b * 4 + 3]);

        u64t a0 = pack2(f0.x, f0.x), a1 = pack2(f1.x, f1.x);
        u64t a2 = pack2(f2.x, f2.x), a3 = pack2(f3.x, f3.x);
        u64t b0 = pack2(f0.y, f0.y), b1 = pack2(f1.y, f1.y);
        u64t b2 = pack2(f2.y, f2.y), b3 = pack2(f3.y, f3.y);

        u64t pvA[8], pvB[8];
#pragma unroll
        for (int hp = 0; hp < 4; hp++) {
            u64t tA = mul2(a0, mwA[hp]);
            tA = fma2(a1, mwA[4 + hp], tA);
            tA = fma2(a2, mwA[8 + hp], tA);
            tA = fma2(a3, mwA[12 + hp], tA);
            float vA0, vA1; unpack2(tA, vA0, vA1);
            vA0 = fmaxf(vA0, 0.0f); vA1 = fmaxf(vA1, 0.0f);
            pvA[2 * hp]     = pack2(vA0, vA0);
            pvA[2 * hp + 1] = pack2(vA1, vA1);

            u64t tB = mul2(b0, mwB[hp]);
            tB = fma2(b1, mwB[4 + hp], tB);
            tB = fma2(b2, mwB[8 + hp], tB);
            tB = fma2(b3, mwB[12 + hp], tB);
            float vB0, vB1; unpack2(tB, vB0, vB1);
            vB0 = fmaxf(vB0, 0.0f); vB1 = fmaxf(vB1, 0.0f);
            pvB[2 * hp]     = pack2(vB0, vB0);
            pvB[2 * hp + 1] = pack2(vB1, vB1);
        }

#pragma unroll
        for (int hp = 0; hp < 4; hp++) {
            u64t oA = sB2[hp], oB = sB2[hp];
#pragma unroll
            for (int hh = 0; hh < 8; hh++) {
                u64t wv = sWt2[hh * 4 + hp];
                oA = fma2(pvA[hh], wv, oA);
                oB = fma2(pvB[hh], wv, oB);
            }
            float oA0, oA1, oB0, oB1;
            unpack2(oA, oA0, oA1);
            unpack2(oB, oB0, oB1);
            stcs_u64(out + ((size_t)(b * 8 + 2 * hp)     << 20) + i0, pack2(oA0, oB0));
            stcs_u64(out + ((size_t)(b * 8 + 2 * hp + 1) << 20) + i0, pack2(oA1, oB1));
        }
    }
}

extern "C" void kernel_launch(void* const* d_in, const int* in_sizes, int n_in,
                              void* d_out, int out_size)
{
    const float* q     = (const float*)d_in[0];
    const float* k     = (const float*)d_in[1];
    const float* masks = (const float*)d_in[2];
    const float* proj  = (const float*)d_in[3];
    const float* hw    = (const float*)d_in[4];
    const float* hb    = (const float*)d_in[5];
    float* out = (float*)d_out;

    cudaFuncSetAttribute(qk_gemm_mma, cudaFuncAttributeMaxDynamicSharedMemorySize, SM_BYTES);

    dim3 g1(N_TOK / 64, N_TOK / 128, NBG);   // (16, 8, 32)
    qk_gemm_mma<<<g1, 128, SM_BYTES>>>(q, k);

    epilogue_kernel<<<NN / 256, 128>>>(masks, proj, hw, hb, out);
}